// round 15
// baseline (speedup 1.0000x reference)
#include <cuda_runtime.h>
#include <math.h>

#define NB 296
#define NT 256
#define NROWS 256      // B*S
#define BBS 128        // S
#define DD 128
#define FF 512
#define VV 1024
#define DK 32
#define LL 2

// ---------------- device scratch ----------------
__device__ float g_x[NROWS*DD];
__device__ float g_qkv[NROWS*384];
__device__ float g_ff[NROWS*FF];
__device__ float g_ffp[4][NROWS*DD];   // head-partials (attn) / k-split partials (FF2)
// transformed weights, K-MAJOR: tw[k*N + n]
__device__ float g_twqkv[LL][DD*384];
__device__ float g_two[LL][DD*DD];
__device__ float g_tw1[LL][DD*FF];
__device__ float g_tw2[LL][FF*DD];
__device__ float g_twout[DD*VV];
// two-level barrier state: 16 cells on distinct 128B lines + root + generation
__device__ unsigned g_cell[16*32];
__device__ unsigned g_root;
__device__ unsigned g_gen;

struct Params {
    const int* tokens; const float* emb; const float* pos;
    const float* Wq; const float* bq; const float* Wk; const float* bk;
    const float* Wv; const float* bv; const float* Wo; const float* bo;
    const float* W1; const float* b1; const float* W2; const float* b2;
    const float* g1; const float* be1; const float* g2; const float* be2;
    const float* Wout; const float* bout;
    float* out;
};

// ---------------- l_mul elementwise transform (bit-twiddled) ----------------
// f(x) = round(x*2^-e * 8) * 2^(2e-3), e = rawexp-126. Exact in tf32.
__device__ __forceinline__ float lmul_f(float x) {
    unsigned bits = __float_as_uint(x);
    int expo = (int)((bits >> 23) & 0xffu);
    if (expo == 0) return 0.0f;
    int e = expo - 126;
    if (e < -40) return 0.0f;
    float m = __int_as_float((bits & 0x807fffffu) | (126u << 23));
    float r = rintf(m * 8.0f);
    return r * __int_as_float((unsigned)(2*e - 3 + 127) << 23);
}

__device__ __forceinline__ float4 lmul_f4(float4 v) {
    float4 o;
    o.x = lmul_f(v.x); o.y = lmul_f(v.y); o.z = lmul_f(v.z); o.w = lmul_f(v.w);
    return o;
}

// ---------------- grid barrier: two-level arrival tree ----------------
// 16 cells (128B apart), ~18-19 CTAs each; cell-masters arrive at root;
// root-master resets state and flips generation. Cuts the 296-way
// single-address atomic serialization (~27cyc/op) to ~2 short chains.
__device__ __forceinline__ void gbar() {
    __syncthreads();
    if (threadIdx.x == 0) {
        __threadfence();
        unsigned gen = *((volatile unsigned*)&g_gen);
        int cell = blockIdx.x & 15;
        unsigned cnt = 18u + (cell < 8 ? 1u : 0u);   // 8*19 + 8*18 = 296
        if (atomicAdd(&g_cell[cell*32], 1u) == cnt - 1u) {
            if (atomicAdd(&g_root, 1u) == 15u) {
                #pragma unroll
                for (int i = 0; i < 16; ++i) g_cell[i*32] = 0u;
                g_root = 0u;
                __threadfence();
                atomicExch(&g_gen, gen + 1u);
            }
        }
        while (*((volatile unsigned*)&g_gen) == gen) __nanosleep(20);
        __threadfence();
    }
    __syncthreads();
}

// ---------------- transform helper: coalesced reads, scattered writes --------
// src row-major [n*K + k] -> dst[k*N + segoff + n]
template<int K>
__device__ __forceinline__ void xf(const float* __restrict__ src,
                                   float* __restrict__ dst,
                                   int N, int segoff, int nElem,
                                   int i0, int step) {
    for (int i = i0; i < nElem; i += step) {
        int n = i / K, k = i - n*K;
        dst[k*N + segoff + n] = lmul_f(src[i]);
    }
}

// ---------------- phase 0 ----------------
__device__ void transform_all(const Params* __restrict__ P) {
    const int t0 = blockIdx.x * NT + threadIdx.x;
    const int STEP = NB * NT;
    for (int l = 0; l < LL; ++l) {
        xf<128>(P->Wq + l*DD*DD, g_twqkv[l], 384,   0, DD*DD, t0, STEP);
        xf<128>(P->Wk + l*DD*DD, g_twqkv[l], 384, 128, DD*DD, t0, STEP);
        xf<128>(P->Wv + l*DD*DD, g_twqkv[l], 384, 256, DD*DD, t0, STEP);
        xf<128>(P->Wo + l*DD*DD, g_two[l],   128,   0, DD*DD, t0, STEP);
        xf<128>(P->W1 + l*FF*DD, g_tw1[l],   512,   0, FF*DD, t0, STEP);
        xf<512>(P->W2 + l*DD*FF, g_tw2[l],   128,   0, DD*FF, t0, STEP);
    }
    xf<128>(P->Wout, g_twout, 1024, 0, VV*DD, t0, STEP);
    for (int i = t0; i < NROWS*DD; i += STEP) {
        int row = i >> 7, d = i & 127;
        int s = row & (BBS - 1);
        g_x[i] = P->emb[P->tokens[row]*DD + d] + P->pos[s*DD + d];
    }
}

// ---------------- tensor-core GEMM tile: 16 rows x 64 cols, K = 128 ----------
// mma.sync.m16n8k8 tf32. 8 warps, each owns an 8-col strip.
// MODE 0: stage f(X rows). MODE 1: rows = g_x + badd + sum(g_ffp) -> LN ->
//         write g_x (identical across col-tiles) and stage f(LN row).
#define WSS 72
template<int MODE>
__device__ __forceinline__ void gemm_mma(
    const float* __restrict__ X, int ldx, int kbeg,
    const float* __restrict__ W, int N,
    const float* __restrict__ bias, int relu,
    const float* __restrict__ badd, const float* __restrict__ gam,
    const float* __restrict__ bet,
    float* __restrict__ Y, int ldy,
    int row0, int col0,
    float* __restrict__ ws /* 128*WSS */, float* __restrict__ xs /* 16*132 */)
{
    const int tid = threadIdx.x;
    const int lane = tid & 31;
    #pragma unroll
    for (int i = 0; i < 8; ++i) {
        int idx = tid + i*NT;
        int k = idx >> 4, c4 = (idx & 15) << 2;
        *(float4*)(ws + k*WSS + c4) =
            *(const float4*)(W + (size_t)(kbeg + k)*N + col0 + c4);
    }
    #pragma unroll
    for (int i = 0; i < 2; ++i) {
        int r = (tid >> 5) + i*8;
        int k4 = lane * 4;
        if (MODE == 0) {
            float4 v = lmul_f4(*(const float4*)(X + (size_t)(row0 + r)*ldx + kbeg + k4));
            *(float4*)(xs + r*132 + k4) = v;
        } else {
            const int grow = row0 + r;
            float4 u = *(const float4*)(g_x + grow*DD + k4);
            float4 bb = *(const float4*)(badd + k4);
            u.x += bb.x; u.y += bb.y; u.z += bb.z; u.w += bb.w;
            #pragma unroll
            for (int ks = 0; ks < 4; ++ks) {
                float4 p = *(const float4*)(g_ffp[ks] + grow*DD + k4);
                u.x += p.x; u.y += p.y; u.z += p.z; u.w += p.w;
            }
            float s  = (u.x + u.y) + (u.z + u.w);
            float sq = fmaf(u.x, u.x, fmaf(u.y, u.y, fmaf(u.z, u.z, u.w*u.w)));
            #pragma unroll
            for (int o = 16; o; o >>= 1) {
                s  += __shfl_xor_sync(0xffffffffu, s, o);
                sq += __shfl_xor_sync(0xffffffffu, sq, o);
            }
            float mean = s * (1.f/128.f);
            float rs = rsqrtf(sq * (1.f/128.f) - mean*mean + 1e-5f);
            float4 gv  = *(const float4*)(gam + k4);
            float4 bev = *(const float4*)(bet + k4);
            float4 ln;
            ln.x = (u.x - mean)*rs*gv.x + bev.x;
            ln.y = (u.y - mean)*rs*gv.y + bev.y;
            ln.z = (u.z - mean)*rs*gv.z + bev.z;
            ln.w = (u.w - mean)*rs*gv.w + bev.w;
            *(float4*)(g_x + grow*DD + k4) = ln;
            *(float4*)(xs + r*132 + k4) = lmul_f4(ln);
        }
    }
    __syncthreads();

    const int w = tid >> 5;
    const int g = lane >> 2;
    const int t = lane & 3;
    const float* xr0 = xs + g*132;
    const float* xr1 = xs + (g + 8)*132;
    const float* wb  = ws + w*8 + g;
    float c0a=0.f,c1a=0.f,c2a=0.f,c3a=0.f;
    float c0b=0.f,c1b=0.f,c2b=0.f,c3b=0.f;
    #pragma unroll
    for (int k0 = 0; k0 < 128; k0 += 16) {
        unsigned a0 = __float_as_uint(xr0[k0 + t]);
        unsigned a1 = __float_as_uint(xr1[k0 + t]);
        unsigned a2 = __float_as_uint(xr0[k0 + 4 + t]);
        unsigned a3 = __float_as_uint(xr1[k0 + 4 + t]);
        unsigned b0 = __float_as_uint(wb[(k0 + t)*WSS]);
        unsigned b1 = __float_as_uint(wb[(k0 + 4 + t)*WSS]);
        asm volatile(
            "mma.sync.aligned.m16n8k8.row.col.f32.tf32.tf32.f32 "
            "{%0,%1,%2,%3}, {%4,%5,%6,%7}, {%8,%9}, {%0,%1,%2,%3};"
            : "+f"(c0a), "+f"(c1a), "+f"(c2a), "+f"(c3a)
            : "r"(a0), "r"(a1), "r"(a2), "r"(a3), "r"(b0), "r"(b1));
        unsigned a4 = __float_as_uint(xr0[k0 + 8 + t]);
        unsigned a5 = __float_as_uint(xr1[k0 + 8 + t]);
        unsigned a6 = __float_as_uint(xr0[k0 + 12 + t]);
        unsigned a7 = __float_as_uint(xr1[k0 + 12 + t]);
        unsigned b2 = __float_as_uint(wb[(k0 + 8 + t)*WSS]);
        unsigned b3 = __float_as_uint(wb[(k0 + 12 + t)*WSS]);
        asm volatile(
            "mma.sync.aligned.m16n8k8.row.col.f32.tf32.tf32.f32 "
            "{%0,%1,%2,%3}, {%4,%5,%6,%7}, {%8,%9}, {%0,%1,%2,%3};"
            : "+f"(c0b), "+f"(c1b), "+f"(c2b), "+f"(c3b)
            : "r"(a4), "r"(a5), "r"(a6), "r"(a7), "r"(b2), "r"(b3));
    }
    float c0 = c0a + c0b, c1 = c1a + c1b, c2 = c2a + c2b, c3 = c3a + c3b;
    int cl = w*8 + 2*t;
    float b0v = bias ? bias[cl]     : 0.f;
    float b1v = bias ? bias[cl + 1] : 0.f;
    c0 += b0v; c1 += b1v; c2 += b0v; c3 += b1v;
    if (relu) {
        c0 = fmaxf(c0, 0.f); c1 = fmaxf(c1, 0.f);
        c2 = fmaxf(c2, 0.f); c3 = fmaxf(c3, 0.f);
    }
    *(float2*)(Y + (size_t)(row0 + g    )*ldy + col0 + cl) = make_float2(c0, c1);
    *(float2*)(Y + (size_t)(row0 + g + 8)*ldy + col0 + cl) = make_float2(c2, c3);
    __syncthreads();
}

// ---------------- attention + O-proj head-partial tile -----------------------
// tile = (b, h, 8-query block); warp per query (8 warps).
// After softmax*V, applies f() (O-proj is an l_mul linear) and computes the
// 8x128 partial f(att_h) @ f(Wo[h*32:,:]) into g_ffp[h].
__device__ void attn_tile(
    const float* __restrict__ qkv, const float* __restrict__ Wo /* k-major */,
    int b, int h, int qb, float* __restrict__ sm)
{
    float* ksh = sm;               // 128*33 = 4224 (later reused for Wo slice)
    float* vsh = sm + 4224;        // 128*33
    float* qsh = sm + 8448;        // 8*32 = 256
    float* psh = sm + 8704;        // 8*132 = 1056
    float* ash = sm + 9760;        // 8*33 = 264
    float* wsh = ksh;              // 32*132 = 4224 (fits)
    const int tid = threadIdx.x;
    const int wid = tid >> 5, lane = tid & 31;
    #pragma unroll
    for (int i = 0; i < 4; ++i) {
        int idx = tid + i*NT;       // 0..1023 = 128 rows x 8 float4
        int j = idx >> 3, d4 = (idx & 7) * 4;
        const float* base = qkv + (size_t)(b*BBS + j)*384 + h*DK + d4;
        float4 kk = *(const float4*)(base + 128);
        float4 vv = *(const float4*)(base + 256);
        float* kd = ksh + j*33 + d4;
        kd[0] = kk.x; kd[1] = kk.y; kd[2] = kk.z; kd[3] = kk.w;
        float* vd = vsh + j*33 + d4;
        vd[0] = vv.x; vd[1] = vv.y; vd[2] = vv.z; vd[3] = vv.w;
    }
    {
        int qi = tid >> 5, d = tid & 31;   // 8*32 = 256 = NT
        qsh[tid] = qkv[(size_t)(b*BBS + qb*8 + qi)*384 + h*DK + d];
    }
    __syncthreads();
    float qr[32];
    #pragma unroll
    for (int d = 0; d < 32; d += 4) {
        float4 t = *(const float4*)(qsh + wid*32 + d);
        qr[d] = t.x; qr[d+1] = t.y; qr[d+2] = t.z; qr[d+3] = t.w;
    }
    const float* k0 = ksh + (lane     )*33;
    const float* k1 = ksh + (lane + 32)*33;
    const float* k2 = ksh + (lane + 64)*33;
    const float* k3 = ksh + (lane + 96)*33;
    float s0 = 0.f, s1 = 0.f, s2 = 0.f, s3 = 0.f;
    #pragma unroll
    for (int d = 0; d < 32; ++d) {
        float qd = qr[d];
        s0 = fmaf(qd, k0[d], s0);
        s1 = fmaf(qd, k1[d], s1);
        s2 = fmaf(qd, k2[d], s2);
        s3 = fmaf(qd, k3[d], s3);
    }
    const float scale = 0.17677669529663687f;  // 1/sqrt(32)
    s0 *= scale; s1 *= scale; s2 *= scale; s3 *= scale;
    float m = fmaxf(fmaxf(s0, s1), fmaxf(s2, s3));
    #pragma unroll
    for (int o = 16; o; o >>= 1) m = fmaxf(m, __shfl_xor_sync(0xffffffffu, m, o));
    float p0 = __expf(s0 - m), p1 = __expf(s1 - m), p2 = __expf(s2 - m), p3 = __expf(s3 - m);
    float lsum = p0 + p1 + p2 + p3;
    #pragma unroll
    for (int o = 16; o; o >>= 1) lsum += __shfl_xor_sync(0xffffffffu, lsum, o);
    float* pp = psh + wid*132;
    pp[lane     ] = p0;
    pp[lane + 32] = p1;
    pp[lane + 64] = p2;
    pp[lane + 96] = p3;
    __syncthreads();                // K reads done; psh complete
    // cooperative Wo slice load into wsh (= ksh region): 32 d x 128 n
    #pragma unroll
    for (int i = 0; i < 4; ++i) {
        int idx = tid + i*NT;       // 0..1023
        int d = idx >> 5, n4 = (idx & 31) * 4;
        *(float4*)(wsh + d*132 + n4) =
            *(const float4*)(Wo + (size_t)(h*DK + d)*DD + n4);
    }
    // softmax * V, then f() for the l_mul O-projection
    {
        float o0 = 0.f, o1 = 0.f, o2 = 0.f, o3 = 0.f;
        #pragma unroll 8
        for (int j = 0; j < 128; j += 4) {
            o0 = fmaf(pp[j+0], vsh[(j+0)*33 + lane], o0);
            o1 = fmaf(pp[j+1], vsh[(j+1)*33 + lane], o1);
            o2 = fmaf(pp[j+2], vsh[(j+2)*33 + lane], o2);
            o3 = fmaf(pp[j+3], vsh[(j+3)*33 + lane], o3);
        }
        ash[wid*33 + lane] = lmul_f(((o0 + o1) + (o2 + o3)) / lsum);
    }
    __syncthreads();
    // O-proj partial: c = tid&127, rg = tid>>7 -> rows rg*4..rg*4+3
    {
        const int c = tid & 127, rg = tid >> 7;
        float a0 = 0.f, a1 = 0.f, a2 = 0.f, a3 = 0.f;
        #pragma unroll 8
        for (int d = 0; d < 32; ++d) {
            float wv = wsh[d*132 + c];
            a0 = fmaf(ash[(rg*4+0)*33 + d], wv, a0);
            a1 = fmaf(ash[(rg*4+1)*33 + d], wv, a1);
            a2 = fmaf(ash[(rg*4+2)*33 + d], wv, a2);
            a3 = fmaf(ash[(rg*4+3)*33 + d], wv, a3);
        }
        float* dst = g_ffp[h] + (size_t)(b*BBS + qb*8 + rg*4)*DD + c;
        dst[0*DD] = a0; dst[1*DD] = a1; dst[2*DD] = a2; dst[3*DD] = a3;
    }
    __syncthreads();
}

// ---------------- the one persistent kernel ----------------
__global__ void __launch_bounds__(NT, 2) model_kernel(Params P) {
    __shared__ __align__(16) float sm[128*WSS + 16*132];   // 45.3KB (attn uses 10KB)
    float* ws = sm;
    float* xs = sm + 128*WSS;
    const int bid = blockIdx.x;

    // P0: weight transforms + embedding
    transform_all(&P);
    gbar();

    for (int l = 0; l < LL; ++l) {
        // P1: QKV fused GEMM — 96 tiles; at l=1 staging applies l0 FF2+res+LN2.
        if (bid < 96) {
            int rt = bid & 15, ct = bid >> 4;
            int col0 = ct * 64;
            int seg = col0 >> 7;
            const float* segb = (seg == 0 ? P.bq : seg == 1 ? P.bk : P.bv)
                                + l*DD + (col0 & 127);
            if (l == 0) {
                gemm_mma<0>(g_x, DD, 0, g_twqkv[l], 384, segb, 0,
                            0, 0, 0, g_qkv, 384, rt*16, col0, ws, xs);
            } else {
                gemm_mma<1>(g_x, DD, 0, g_twqkv[l], 384, segb, 0,
                            P.b2, P.g2, P.be2,
                            g_qkv, 384, rt*16, col0, ws, xs);
            }
        }
        gbar();

        // P2: attention + O-proj head partials — 128 tiles (b, h, 8-query)
        if (bid < 128) {
            int b = bid >> 6, h = (bid >> 4) & 3, qb = bid & 15;
            attn_tile(g_qkv, g_two[l], b, h, qb, sm);
        }
        gbar();

        // P3: FF1 + relu — 128 tiles; staging applies oproj-combine+res+LN1.
        if (bid < 128) {
            int rt = bid & 15, ct = bid >> 4;
            gemm_mma<1>(g_x, DD, 0, g_tw1[l], FF, P.b1 + l*FF + ct*64, 1,
                        P.bo + l*DD, P.g1 + l*DD, P.be1 + l*DD,
                        g_ff, FF, rt*16, ct*64, ws, xs);
        }
        gbar();

        // P4: FF2 k-split partials — 128 tiles (16 rt x 2 col64 x 4 k-chunks)
        if (bid < 128) {
            int rt = bid & 15, ct = (bid >> 4) & 1, kc = bid >> 5;
            gemm_mma<0>(g_ff, FF, kc*128, g_tw2[l], DD, (const float*)0, 0,
                        0, 0, 0, g_ffp[kc], DD, rt*16, ct*64, ws, xs);
        }
        gbar();
    }

    // P5: final vocab projection — 256 tiles; staging applies l1 FF2+res+LN2.
    if (bid < 256) {
        int rt = bid & 15, ct = bid >> 4;
        gemm_mma<1>(g_x, DD, 0, g_twout, VV, P.bout + ct*64, 0,
                    P.b2 + DD, P.g2 + DD, P.be2 + DD,
                    P.out, VV, rt*16, ct*64, ws, xs);
    }
}

extern "C" void kernel_launch(void* const* d_in, const int* in_sizes, int n_in,
                              void* d_out, int out_size) {
    Params P;
    P.tokens = (const int*)  d_in[0];
    P.emb    = (const float*)d_in[1];
    P.pos    = (const float*)d_in[2];
    P.Wq     = (const float*)d_in[3];
    P.bq     = (const float*)d_in[4];
    P.Wk     = (const float*)d_in[5];
    P.bk     = (const float*)d_in[6];
    P.Wv     = (const float*)d_in[7];
    P.bv     = (const float*)d_in[8];
    P.Wo     = (const float*)d_in[9];
    P.bo     = (const float*)d_in[10];
    P.W1     = (const float*)d_in[11];
    P.b1     = (const float*)d_in[12];
    P.W2     = (const float*)d_in[13];
    P.b2     = (const float*)d_in[14];
    P.g1     = (const float*)d_in[15];
    P.be1    = (const float*)d_in[16];
    P.g2     = (const float*)d_in[17];
    P.be2    = (const float*)d_in[18];
    P.Wout   = (const float*)d_in[19];
    P.bout   = (const float*)d_in[20];
    P.out    = (float*)d_out;

    model_kernel<<<NB, NT>>>(P);
}

// round 16
// speedup vs baseline: 1.1167x; 1.1167x over previous
#include <cuda_runtime.h>
#include <math.h>

#define NB 296
#define NT 256
#define NROWS 256      // B*S
#define BBS 128        // S
#define DD 128
#define FF 512
#define VV 1024
#define DK 32
#define LL 2

// ---------------- device scratch ----------------
__device__ float g_x[NROWS*DD];
__device__ float g_qkv[NROWS*384];
__device__ float g_ff[NROWS*FF];
__device__ float g_ffp[4][NROWS*DD];   // head-partials (attn) / k-split partials (FF2)
__device__ unsigned g_count;
__device__ unsigned g_gen;

struct Params {
    const int* tokens; const float* emb; const float* pos;
    const float* Wq; const float* bq; const float* Wk; const float* bk;
    const float* Wv; const float* bv; const float* Wo; const float* bo;
    const float* W1; const float* b1; const float* W2; const float* b2;
    const float* g1; const float* be1; const float* g2; const float* be2;
    const float* Wout; const float* bout;
    float* out;
};

// ---------------- l_mul elementwise transform (bit-twiddled) ----------------
// f(x) = round(x*2^-e * 8) * 2^(2e-3), e = rawexp-126. Exact in tf32.
__device__ __forceinline__ float lmul_f(float x) {
    unsigned bits = __float_as_uint(x);
    int expo = (int)((bits >> 23) & 0xffu);
    if (expo == 0) return 0.0f;
    int e = expo - 126;
    if (e < -40) return 0.0f;
    float m = __int_as_float((bits & 0x807fffffu) | (126u << 23));
    float r = rintf(m * 8.0f);
    return r * __int_as_float((unsigned)(2*e - 3 + 127) << 23);
}

__device__ __forceinline__ float4 lmul_f4(float4 v) {
    float4 o;
    o.x = lmul_f(v.x); o.y = lmul_f(v.y); o.z = lmul_f(v.z); o.w = lmul_f(v.w);
    return o;
}

// ---------------- flat grid barrier (proven R14 config) ----------------
__device__ __forceinline__ void gbar() {
    __syncthreads();
    if (threadIdx.x == 0) {
        __threadfence();
        unsigned gen = *((volatile unsigned*)&g_gen);
        if (atomicAdd(&g_count, 1u) == NB - 1u) {
            atomicExch(&g_count, 0u);
            __threadfence();
            atomicExch(&g_gen, gen + 1u);
        } else {
            while (*((volatile unsigned*)&g_gen) == gen) __nanosleep(20);
        }
        __threadfence();
    }
    __syncthreads();
}

// ---------------- tensor-core GEMM tile: 16 rows x 64 cols, K-chunk 128 ------
// RAW n-major weights: tile loads W[col0n+n][kbeg..kbeg+127] coalesced,
// applies f() in registers, stores n-major into ws (stride 132).
// B-fragment read ws[(w*8+g)*132 + k] is bank-conflict-free (132%32 == 4).
// MODE 0: stage f(X rows).
// MODE 1: rows = g_x + badd + sum(g_ffp) -> LN -> write g_x + stage f(LN).
// MODE 2: rows = emb[token]+pos -> write g_x + stage f(row)   (embedding).
template<int MODE>
__device__ __forceinline__ void gemm_mma(
    const float* __restrict__ X, int ldx, int kbeg,
    const float* __restrict__ Wraw, int ldw, int col0n,
    const float* __restrict__ bias, int relu,
    const float* __restrict__ badd, const float* __restrict__ gam,
    const float* __restrict__ bet,
    const int* __restrict__ tokens, const float* __restrict__ emb,
    const float* __restrict__ pos,
    float* __restrict__ Y, int ldy,
    int row0, int col0,
    float* __restrict__ ws /* 64*132 */, float* __restrict__ xs /* 16*132 */)
{
    const int tid = threadIdx.x;
    const int lane = tid & 31;
    // weight tile: 64 n-rows x 128 k, coalesced along k, f() on the fly
    #pragma unroll
    for (int i = 0; i < 8; ++i) {
        int idx = tid + i*NT;                 // 0..2047
        int n = idx >> 5, k4 = (idx & 31) << 2;
        float4 v = lmul_f4(*(const float4*)(Wraw + (size_t)(col0n + n)*ldw + kbeg + k4));
        *(float4*)(ws + n*132 + k4) = v;
    }
    // staging: one warp per row, float4 per lane (16 rows)
    #pragma unroll
    for (int i = 0; i < 2; ++i) {
        int r = (tid >> 5) + i*8;
        int k4 = lane * 4;
        const int grow = row0 + r;
        if (MODE == 0) {
            float4 v = lmul_f4(*(const float4*)(X + (size_t)grow*ldx + kbeg + k4));
            *(float4*)(xs + r*132 + k4) = v;
        } else if (MODE == 2) {
            int tok = tokens[grow];
            float4 e = *(const float4*)(emb + (size_t)tok*DD + k4);
            float4 p = *(const float4*)(pos + (size_t)(grow & (BBS-1))*DD + k4);
            float4 u;
            u.x = e.x + p.x; u.y = e.y + p.y; u.z = e.z + p.z; u.w = e.w + p.w;
            *(float4*)(g_x + grow*DD + k4) = u;   // identical across col-tiles
            *(float4*)(xs + r*132 + k4) = lmul_f4(u);
        } else {
            float4 u = *(const float4*)(g_x + grow*DD + k4);
            float4 bb = *(const float4*)(badd + k4);
            u.x += bb.x; u.y += bb.y; u.z += bb.z; u.w += bb.w;
            #pragma unroll
            for (int ks = 0; ks < 4; ++ks) {
                float4 p = *(const float4*)(g_ffp[ks] + grow*DD + k4);
                u.x += p.x; u.y += p.y; u.z += p.z; u.w += p.w;
            }
            float s  = (u.x + u.y) + (u.z + u.w);
            float sq = fmaf(u.x, u.x, fmaf(u.y, u.y, fmaf(u.z, u.z, u.w*u.w)));
            #pragma unroll
            for (int o = 16; o; o >>= 1) {
                s  += __shfl_xor_sync(0xffffffffu, s, o);
                sq += __shfl_xor_sync(0xffffffffu, sq, o);
            }
            float mean = s * (1.f/128.f);
            float rs = rsqrtf(sq * (1.f/128.f) - mean*mean + 1e-5f);
            float4 gv  = *(const float4*)(gam + k4);
            float4 bev = *(const float4*)(bet + k4);
            float4 ln;
            ln.x = (u.x - mean)*rs*gv.x + bev.x;
            ln.y = (u.y - mean)*rs*gv.y + bev.y;
            ln.z = (u.z - mean)*rs*gv.z + bev.z;
            ln.w = (u.w - mean)*rs*gv.w + bev.w;
            *(float4*)(g_x + grow*DD + k4) = ln;   // identical across col-tiles
            *(float4*)(xs + r*132 + k4) = lmul_f4(ln);
        }
    }
    __syncthreads();

    const int w = tid >> 5;
    const int g = lane >> 2;
    const int t = lane & 3;
    const float* xr0 = xs + g*132;
    const float* xr1 = xs + (g + 8)*132;
    const float* wb  = ws + (w*8 + g)*132;     // n-major weight row
    float c0a=0.f,c1a=0.f,c2a=0.f,c3a=0.f;
    float c0b=0.f,c1b=0.f,c2b=0.f,c3b=0.f;
    #pragma unroll
    for (int k0 = 0; k0 < 128; k0 += 16) {
        unsigned a0 = __float_as_uint(xr0[k0 + t]);
        unsigned a1 = __float_as_uint(xr1[k0 + t]);
        unsigned a2 = __float_as_uint(xr0[k0 + 4 + t]);
        unsigned a3 = __float_as_uint(xr1[k0 + 4 + t]);
        unsigned b0 = __float_as_uint(wb[k0 + t]);
        unsigned b1 = __float_as_uint(wb[k0 + 4 + t]);
        asm volatile(
            "mma.sync.aligned.m16n8k8.row.col.f32.tf32.tf32.f32 "
            "{%0,%1,%2,%3}, {%4,%5,%6,%7}, {%8,%9}, {%0,%1,%2,%3};"
            : "+f"(c0a), "+f"(c1a), "+f"(c2a), "+f"(c3a)
            : "r"(a0), "r"(a1), "r"(a2), "r"(a3), "r"(b0), "r"(b1));
        unsigned a4 = __float_as_uint(xr0[k0 + 8 + t]);
        unsigned a5 = __float_as_uint(xr1[k0 + 8 + t]);
        unsigned a6 = __float_as_uint(xr0[k0 + 12 + t]);
        unsigned a7 = __float_as_uint(xr1[k0 + 12 + t]);
        unsigned b2 = __float_as_uint(wb[k0 + 8 + t]);
        unsigned b3 = __float_as_uint(wb[k0 + 12 + t]);
        asm volatile(
            "mma.sync.aligned.m16n8k8.row.col.f32.tf32.tf32.f32 "
            "{%0,%1,%2,%3}, {%4,%5,%6,%7}, {%8,%9}, {%0,%1,%2,%3};"
            : "+f"(c0b), "+f"(c1b), "+f"(c2b), "+f"(c3b)
            : "r"(a4), "r"(a5), "r"(a6), "r"(a7), "r"(b2), "r"(b3));
    }
    float c0 = c0a + c0b, c1 = c1a + c1b, c2 = c2a + c2b, c3 = c3a + c3b;
    int cl = w*8 + 2*t;
    float b0v = bias ? bias[cl]     : 0.f;
    float b1v = bias ? bias[cl + 1] : 0.f;
    c0 += b0v; c1 += b1v; c2 += b0v; c3 += b1v;
    if (relu) {
        c0 = fmaxf(c0, 0.f); c1 = fmaxf(c1, 0.f);
        c2 = fmaxf(c2, 0.f); c3 = fmaxf(c3, 0.f);
    }
    *(float2*)(Y + (size_t)(row0 + g    )*ldy + col0 + cl) = make_float2(c0, c1);
    *(float2*)(Y + (size_t)(row0 + g + 8)*ldy + col0 + cl) = make_float2(c2, c3);
    __syncthreads();
}

// ---------------- attention + O-proj head-partial tile -----------------------
// tile = (b, h, 8-query block); warp per query (8 warps).
// After softmax*V, applies f() (O-proj is an l_mul linear) and computes the
// 8x128 partial f(att_h) @ f(Wo[:, h*32:]) into g_ffp[h]. Raw Wo transformed
// on load into the dead K buffer.
__device__ void attn_tile(
    const float* __restrict__ qkv, const float* __restrict__ Wo /* raw [n][k] */,
    int b, int h, int qb, float* __restrict__ sm)
{
    float* ksh = sm;               // 128*33 = 4224 (later reused for Wo slice)
    float* vsh = sm + 4224;        // 128*33
    float* qsh = sm + 8448;        // 8*32 = 256
    float* psh = sm + 8704;        // 8*132 = 1056
    float* ash = sm + 9760;        // 8*33 = 264
    float* wsh = ksh;              // 32 d x 128 n, stride 132 -> 4224 (fits)
    const int tid = threadIdx.x;
    const int wid = tid >> 5, lane = tid & 31;
    #pragma unroll
    for (int i = 0; i < 4; ++i) {
        int idx = tid + i*NT;       // 0..1023 = 128 rows x 8 float4
        int j = idx >> 3, d4 = (idx & 7) * 4;
        const float* base = qkv + (size_t)(b*BBS + j)*384 + h*DK + d4;
        float4 kk = *(const float4*)(base + 128);
        float4 vv = *(const float4*)(base + 256);
        float* kd = ksh + j*33 + d4;
        kd[0] = kk.x; kd[1] = kk.y; kd[2] = kk.z; kd[3] = kk.w;
        float* vd = vsh + j*33 + d4;
        vd[0] = vv.x; vd[1] = vv.y; vd[2] = vv.z; vd[3] = vv.w;
    }
    {
        int qi = tid >> 5, d = tid & 31;   // 8*32 = 256 = NT
        qsh[tid] = qkv[(size_t)(b*BBS + qb*8 + qi)*384 + h*DK + d];
    }
    __syncthreads();
    float qr[32];
    #pragma unroll
    for (int d = 0; d < 32; d += 4) {
        float4 t = *(const float4*)(qsh + wid*32 + d);
        qr[d] = t.x; qr[d+1] = t.y; qr[d+2] = t.z; qr[d+3] = t.w;
    }
    const float* k0 = ksh + (lane     )*33;
    const float* k1 = ksh + (lane + 32)*33;
    const float* k2 = ksh + (lane + 64)*33;
    const float* k3 = ksh + (lane + 96)*33;
    float s0 = 0.f, s1 = 0.f, s2 = 0.f, s3 = 0.f;
    #pragma unroll
    for (int d = 0; d < 32; ++d) {
        float qd = qr[d];
        s0 = fmaf(qd, k0[d], s0);
        s1 = fmaf(qd, k1[d], s1);
        s2 = fmaf(qd, k2[d], s2);
        s3 = fmaf(qd, k3[d], s3);
    }
    const float scale = 0.17677669529663687f;  // 1/sqrt(32)
    s0 *= scale; s1 *= scale; s2 *= scale; s3 *= scale;
    float m = fmaxf(fmaxf(s0, s1), fmaxf(s2, s3));
    #pragma unroll
    for (int o = 16; o; o >>= 1) m = fmaxf(m, __shfl_xor_sync(0xffffffffu, m, o));
    float p0 = __expf(s0 - m), p1 = __expf(s1 - m), p2 = __expf(s2 - m), p3 = __expf(s3 - m);
    float lsum = p0 + p1 + p2 + p3;
    #pragma unroll
    for (int o = 16; o; o >>= 1) lsum += __shfl_xor_sync(0xffffffffu, lsum, o);
    float* pp = psh + wid*132;
    pp[lane     ] = p0;
    pp[lane + 32] = p1;
    pp[lane + 64] = p2;
    pp[lane + 96] = p3;
    __syncthreads();                // K reads done; psh complete
    // Wo slice: raw [n][128], need wsh[d*132 + n] = f(Wo[n][h*32+d])
    #pragma unroll
    for (int i = 0; i < 4; ++i) {
        int idx = tid + i*NT;       // 0..1023 = 128 n x 8 float4(d)
        int n = idx >> 3, d4 = (idx & 7) * 4;
        float4 v = lmul_f4(*(const float4*)(Wo + (size_t)n*DD + h*DK + d4));
        wsh[(d4+0)*132 + n] = v.x;
        wsh[(d4+1)*132 + n] = v.y;
        wsh[(d4+2)*132 + n] = v.z;
        wsh[(d4+3)*132 + n] = v.w;
    }
    // softmax * V, then f() for the l_mul O-projection
    {
        float o0 = 0.f, o1 = 0.f, o2 = 0.f, o3 = 0.f;
        #pragma unroll 8
        for (int j = 0; j < 128; j += 4) {
            o0 = fmaf(pp[j+0], vsh[(j+0)*33 + lane], o0);
            o1 = fmaf(pp[j+1], vsh[(j+1)*33 + lane], o1);
            o2 = fmaf(pp[j+2], vsh[(j+2)*33 + lane], o2);
            o3 = fmaf(pp[j+3], vsh[(j+3)*33 + lane], o3);
        }
        ash[wid*33 + lane] = lmul_f(((o0 + o1) + (o2 + o3)) / lsum);
    }
    __syncthreads();
    // O-proj partial: c = tid&127, rg = tid>>7 -> rows rg*4..rg*4+3
    {
        const int c = tid & 127, rg = tid >> 7;
        float a0 = 0.f, a1 = 0.f, a2 = 0.f, a3 = 0.f;
        #pragma unroll 8
        for (int d = 0; d < 32; ++d) {
            float wv = wsh[d*132 + c];
            a0 = fmaf(ash[(rg*4+0)*33 + d], wv, a0);
            a1 = fmaf(ash[(rg*4+1)*33 + d], wv, a1);
            a2 = fmaf(ash[(rg*4+2)*33 + d], wv, a2);
            a3 = fmaf(ash[(rg*4+3)*33 + d], wv, a3);
        }
        float* dst = g_ffp[h] + (size_t)(b*BBS + qb*8 + rg*4)*DD + c;
        dst[0*DD] = a0; dst[1*DD] = a1; dst[2*DD] = a2; dst[3*DD] = a3;
    }
    __syncthreads();
}

// ---------------- the one persistent kernel ----------------
__global__ void __launch_bounds__(NT, 2) model_kernel(Params P) {
    __shared__ __align__(16) float sm[64*132 + 16*132];   // 42.2KB (attn uses 10KB)
    float* ws = sm;
    float* xs = sm + 64*132;
    const int bid = blockIdx.x;

    for (int l = 0; l < LL; ++l) {
        // P1: QKV fused GEMM — 96 tiles (16 rowtiles(16r) x 6 col64).
        //     l=0: staging does embedding (MODE 2).
        //     l=1: staging applies l0 FF2-combine + residual + LN2 (MODE 1).
        if (bid < 96) {
            int rt = bid & 15, ct = bid >> 4;
            int col0 = ct * 64;
            int seg = col0 >> 7;
            const float* wsrc = (seg == 0 ? P.Wq : seg == 1 ? P.Wk : P.Wv) + l*DD*DD;
            const float* segb = (seg == 0 ? P.bq : seg == 1 ? P.bk : P.bv)
                                + l*DD + (col0 & 127);
            if (l == 0) {
                gemm_mma<2>((const float*)0, 0, 0, wsrc, DD, col0 & 127, segb, 0,
                            0, 0, 0, P.tokens, P.emb, P.pos,
                            g_qkv, 384, rt*16, col0, ws, xs);
            } else {
                gemm_mma<1>((const float*)0, 0, 0, wsrc, DD, col0 & 127, segb, 0,
                            P.b2, P.g2, P.be2, 0, 0, 0,
                            g_qkv, 384, rt*16, col0, ws, xs);
            }
        }
        gbar();

        // P2: attention + O-proj head partials — 128 tiles (b, h, 8-query)
        if (bid < 128) {
            int b = bid >> 6, h = (bid >> 4) & 3, qb = bid & 15;
            attn_tile(g_qkv, P.Wo + l*DD*DD, b, h, qb, sm);
        }
        gbar();

        // P3: FF1 + relu — 128 tiles; staging applies oproj-combine+res+LN1.
        if (bid < 128) {
            int rt = bid & 15, ct = bid >> 4;
            gemm_mma<1>((const float*)0, 0, 0, P.W1 + l*FF*DD, DD, ct*64,
                        P.b1 + l*FF + ct*64, 1,
                        P.bo + l*DD, P.g1 + l*DD, P.be1 + l*DD, 0, 0, 0,
                        g_ff, FF, rt*16, ct*64, ws, xs);
        }
        gbar();

        // P4: FF2 k-split partials — 128 tiles (16 rt x 2 col64 x 4 k-chunks)
        if (bid < 128) {
            int rt = bid & 15, ct = (bid >> 4) & 1, kc = bid >> 5;
            gemm_mma<0>(g_ff, FF, kc*128, P.W2 + l*DD*FF, FF, ct*64,
                        (const float*)0, 0,
                        0, 0, 0, 0, 0, 0,
                        g_ffp[kc], DD, rt*16, ct*64, ws, xs);
        }
        gbar();
    }

    // P5: final vocab projection — 256 tiles; staging applies l1 FF2+res+LN2.
    if (bid < 256) {
        int rt = bid & 15, ct = bid >> 4;
        gemm_mma<1>((const float*)0, 0, 0, P.Wout, DD, ct*64,
                    P.bout + ct*64, 0,
                    P.b2 + DD, P.g2 + DD, P.be2 + DD, 0, 0, 0,
                    P.out, VV, rt*16, ct*64, ws, xs);
    }
}

extern "C" void kernel_launch(void* const* d_in, const int* in_sizes, int n_in,
                              void* d_out, int out_size) {
    Params P;
    P.tokens = (const int*)  d_in[0];
    P.emb    = (const float*)d_in[1];
    P.pos    = (const float*)d_in[2];
    P.Wq     = (const float*)d_in[3];
    P.bq     = (const float*)d_in[4];
    P.Wk     = (const float*)d_in[5];
    P.bk     = (const float*)d_in[6];
    P.Wv     = (const float*)d_in[7];
    P.bv     = (const float*)d_in[8];
    P.Wo     = (const float*)d_in[9];
    P.bo     = (const float*)d_in[10];
    P.W1     = (const float*)d_in[11];
    P.b1     = (const float*)d_in[12];
    P.W2     = (const float*)d_in[13];
    P.b2     = (const float*)d_in[14];
    P.g1     = (const float*)d_in[15];
    P.be1    = (const float*)d_in[16];
    P.g2     = (const float*)d_in[17];
    P.be2    = (const float*)d_in[18];
    P.Wout   = (const float*)d_in[19];
    P.bout   = (const float*)d_in[20];
    P.out    = (float*)d_out;

    model_kernel<<<NB, NT>>>(P);
}